// round 16
// baseline (speedup 1.0000x reference)
#include <cuda_runtime.h>

// Shapes: L=4, B=8, C=256, H=W=64
#define LN 4
#define BN 8
#define CN 256
#define HW 4096
#define GRIDN (LN*CN)            // 1024 blocks: one slab (l, c) per batch
#define TPB 256

// Monotonic state: NEVER reset (graph-replay safe, no init launch needed).
__device__ unsigned g_gap_bits[LN*BN*CN];   // gap values as bits (stcg/ldcg)
__device__ unsigned g_ready[BN];            // accumulates GRIDN per replay
__device__ unsigned g_epoch_tk;             // replay epoch ticket

__device__ __forceinline__ unsigned poll_cg(const unsigned* p) {
    unsigned r;
    asm volatile("ld.global.cg.u32 %0, [%1];" : "=r"(r) : "l"(p));
    return r;
}

// A-phase: stream-read slab (l,b,c) (lines park in L2), block-reduce,
// publish gap + ready ticket.
__device__ __forceinline__ void a_phase(const float* __restrict__ in,
                                        int l, int c, int b, int tid,
                                        float* s_warp) {
    const float4* p = reinterpret_cast<const float4*>(in)
                    + (size_t)((l * BN + b) * CN + c) * 1024;
    float acc = 0.0f;
#pragma unroll
    for (int k = 0; k < 4; ++k) {
        float4 v = __ldg(p + tid + k * 256);    // default: park line in L2
        acc += (v.x + v.y) + (v.z + v.w);
    }
#pragma unroll
    for (int off = 16; off; off >>= 1)
        acc += __shfl_down_sync(0xffffffffu, acc, off);
    if ((tid & 31) == 0) s_warp[tid >> 5] = acc;
    __syncthreads();
    if (tid == 0) {
        float t = 0.0f;
#pragma unroll
        for (int w = 0; w < 8; ++w) t += s_warp[w];
        t *= (1.0f / (float)HW);
        asm volatile("st.global.cg.u32 [%0], %1;"
                     :: "l"(&g_gap_bits[(l * BN + b) * CN + c]),
                        "r"(__float_as_uint(t)));
        __threadfence();                        // gap visible before ticket
        atomicAdd(&g_ready[b], 1u);
    }
    __syncthreads();
}

// Block (l = bid>>8, c = bid&255). Pipeline (9 iterations):
//   pre:  A(0), A(1)
//   i=1..8: A(i+1) [if <=7], then B(i-1)
// ready[b] reaches target at iteration b-1; polled at iteration b+1 -> the
// 2-iteration slack R14 validated, with one less drain iteration.
__global__ __launch_bounds__(TPB, 8) void main_kernel(const float* __restrict__ in,
                                                      const float* __restrict__ Wlin,
                                                      float* __restrict__ out) {
    const int bid = blockIdx.x;
    const int c   = bid & 255;
    const int l   = bid >> 8;
    const int tid = threadIdx.x;

    __shared__ float    s_warp[8];
    __shared__ float    s_sc[LN];
    __shared__ unsigned s_target;

    // Per-replay epoch: GRIDN increments per launch, replays are serialized,
    // so old/GRIDN is identical for all blocks of one launch.
    if (tid == 0) {
        unsigned e = atomicAdd(&g_epoch_tk, 1u) / (unsigned)GRIDN;
        s_target = (e + 1u) * (unsigned)GRIDN;  // g_ready[b] value when batch b done
    }
    __syncthreads();
    const unsigned target = s_target;

    // ---- Fill: read batches 0 and 1 ----
    a_phase(in, l, c, 0, tid, s_warp);
    a_phase(in, l, c, 1, tid, s_warp);

    for (int i = 1; i <= 8; ++i) {
        // ---- A(i+1) ----
        if (i + 1 <= BN - 1) a_phase(in, l, c, i + 1, tid, s_warp);

        // ---- B(i-1) ----
        const int bb = i - 1;
        if (tid == 0)
            while (poll_cg(&g_ready[bb]) < target) __nanosleep(64);
        __syncthreads();

        // Scores: warp w -> level w; lane j covers c' = j*8..j*8+7.
        const int w = tid >> 5, j = tid & 31;
        if (w < LN) {
            const float* gb = reinterpret_cast<const float*>(g_gap_bits)
                            + (w * BN + bb) * CN;
            float g[8];
#pragma unroll
            for (int k = 0; k < 8; ++k) {
                unsigned u;
                asm volatile("ld.global.cg.u32 %0, [%1];"
                             : "=r"(u) : "l"((const unsigned*)gb + j * 8 + k));
                g[k] = __uint_as_float(u);
            }
            const float4* wp = reinterpret_cast<const float4*>(Wlin + (size_t)c * CN) + j * 2;
            float4 w0 = __ldg(wp), w1 = __ldg(wp + 1);
            float sc = g[0] * w0.x + g[1] * w0.y + g[2] * w0.z + g[3] * w0.w
                     + g[4] * w1.x + g[5] * w1.y + g[6] * w1.z + g[7] * w1.w;
#pragma unroll
            for (int off = 16; off; off >>= 1)
                sc += __shfl_down_sync(0xffffffffu, sc, off);
            if (j == 0) s_sc[w] = sc;
        }
        __syncthreads();

        float m  = fmaxf(fmaxf(s_sc[0], s_sc[1]), fmaxf(s_sc[2], s_sc[3]));
        float e0 = __expf(s_sc[0] - m), e1 = __expf(s_sc[1] - m);
        float e2 = __expf(s_sc[2] - m), e3 = __expf(s_sc[3] - m);
        float inv = 1.0f / ((e0 + e1) + (e2 + e3));
        const float a = (l == 0 ? e0 : l == 1 ? e1 : l == 2 ? e2 : e3) * inv;

        // Re-read batch-bb slab (parked in L2 two iterations ago), store.
        const size_t slab = (size_t)((l * BN + bb) * CN + c);
        const float4* pi = reinterpret_cast<const float4*>(in)  + slab * 1024;
        float4*       po = reinterpret_cast<float4*>(out)       + slab * 1024;
#pragma unroll
        for (int k = 0; k < 4; ++k) {
            float4 v = __ldcs(pi + tid + k * 256);   // dead after read
            v.x *= a; v.y *= a; v.z *= a; v.w *= a;
            __stcs(po + tid + k * 256, v);           // evict-first
        }
        __syncthreads();   // protect s_warp / s_sc across iterations
    }
}

extern "C" void kernel_launch(void* const* d_in, const int* in_sizes, int n_in,
                              void* d_out, int out_size) {
    const float* in   = (const float*)d_in[0];   // [4,8,256,64,64]
    const float* Wlin = (const float*)d_in[1];   // [256,256]
    float* out = (float*)d_out;

    main_kernel<<<GRIDN, TPB>>>(in, Wlin, out);
}

// round 17
// speedup vs baseline: 1.2865x; 1.2865x over previous
#include <cuda_runtime.h>

// Shapes: L=4, B=8, C=256, H=W=64
#define LN 4
#define BN 8
#define CN 256
#define HW 4096
#define GRIDN (LN*CN)            // 1024 blocks: one slab (l, c) per batch
#define TPB 256
#define LAG 2                    // finish batch b-2 while reading batch b

// Monotonic state: NEVER reset (graph-replay safe, no init launch).
__device__ float    g_gap[LN*BN*CN];
__device__ unsigned g_ready[BN];     // grows by GRIDN per replay
__device__ unsigned g_epoch_tk;      // replay epoch ticket

__device__ __forceinline__ unsigned poll_cg(const unsigned* p) {
    unsigned r;
    asm volatile("ld.global.cg.u32 %0, [%1];" : "=r"(r) : "l"(p));
    return r;
}

// ===== EXACT R14 structure; only the flag target is epoch-derived. =====
// Block (l = bid>>8, c = bid&255) owns slab (l, b, c) for every batch b.
// Iteration b: [A] stream-read batch-b slab (parks lines in L2), reduce,
//                  publish gap + ticket;
//              [B] finish batch b-LAG: wait ticket (usually already set),
//                  scores + softmax, re-read slab from L2, scale, store.
__global__ __launch_bounds__(TPB, 8) void main_kernel(const float* __restrict__ in,
                                                      const float* __restrict__ Wlin,
                                                      float* __restrict__ out) {
    const int bid = blockIdx.x;
    const int c   = bid & 255;
    const int l   = bid >> 8;
    const int tid = threadIdx.x;

    __shared__ float    s_warp[8];
    __shared__ float    s_sc[LN];
    __shared__ unsigned s_target;

    // Per-replay epoch: g_epoch_tk grows by GRIDN per launch; replays are
    // serialized, so tk/GRIDN is identical for every block of one launch.
    if (tid == 0) {
        unsigned e = atomicAdd(&g_epoch_tk, 1u) / (unsigned)GRIDN;
        s_target = (e + 1u) * (unsigned)GRIDN;   // g_ready[b] when batch b done
    }
    __syncthreads();
    const unsigned target = s_target;

    for (int b = 0; b < BN + LAG; ++b) {
        // ---- [A] read + reduce batch-b slab, publish ----
        if (b < BN) {
            const float4* p = reinterpret_cast<const float4*>(in)
                            + (size_t)((l * BN + b) * CN + c) * 1024;
            float acc = 0.0f;
#pragma unroll
            for (int k = 0; k < 4; ++k) {
                float4 v = __ldg(p + tid + k * 256);   // default: park line in L2
                acc += (v.x + v.y) + (v.z + v.w);
            }
#pragma unroll
            for (int off = 16; off; off >>= 1)
                acc += __shfl_down_sync(0xffffffffu, acc, off);
            if ((tid & 31) == 0) s_warp[tid >> 5] = acc;
            __syncthreads();
            if (tid == 0) {
                float t = 0.0f;
#pragma unroll
                for (int w = 0; w < 8; ++w) t += s_warp[w];
                __stcg(&g_gap[(l * BN + b) * CN + c], t * (1.0f / (float)HW));
                __threadfence();                       // gap before ticket
                atomicAdd(&g_ready[b], 1u);
            }
        }

        // ---- [B] finish batch b-LAG ----
        if (b >= LAG) {
            const int bb = b - LAG;
            if (tid == 0)
                while (poll_cg(&g_ready[bb]) < target) __nanosleep(64);
            __syncthreads();

            // Scores: warp w -> level w; lane j covers c' = j*8..j*8+7.
            const int w = tid >> 5, j = tid & 31;
            if (w < LN) {
                const float4* gp = reinterpret_cast<const float4*>(g_gap + (w * BN + bb) * CN) + j * 2;
                const float4* wp = reinterpret_cast<const float4*>(Wlin + (size_t)c * CN) + j * 2;
                float4 g0 = gp[0], g1 = gp[1];
                float4 w0 = __ldg(wp), w1 = __ldg(wp + 1);
                float sc = g0.x * w0.x + g0.y * w0.y + g0.z * w0.z + g0.w * w0.w
                         + g1.x * w1.x + g1.y * w1.y + g1.z * w1.z + g1.w * w1.w;
#pragma unroll
                for (int off = 16; off; off >>= 1)
                    sc += __shfl_down_sync(0xffffffffu, sc, off);
                if (j == 0) s_sc[w] = sc;
            }
            __syncthreads();

            float m  = fmaxf(fmaxf(s_sc[0], s_sc[1]), fmaxf(s_sc[2], s_sc[3]));
            float e0 = __expf(s_sc[0] - m), e1 = __expf(s_sc[1] - m);
            float e2 = __expf(s_sc[2] - m), e3 = __expf(s_sc[3] - m);
            float inv = 1.0f / ((e0 + e1) + (e2 + e3));
            const float a = (l == 0 ? e0 : l == 1 ? e1 : l == 2 ? e2 : e3) * inv;

            // Re-read batch-bb slab (parked in L2 two iterations ago), store.
            const size_t slab = (size_t)((l * BN + bb) * CN + c);
            const float4* pi = reinterpret_cast<const float4*>(in)  + slab * 1024;
            float4*       po = reinterpret_cast<float4*>(out)       + slab * 1024;
#pragma unroll
            for (int k = 0; k < 4; ++k) {
                float4 v = __ldcs(pi + tid + k * 256);   // dead after read
                v.x *= a; v.y *= a; v.z *= a; v.w *= a;
                __stcs(po + tid + k * 256, v);           // evict-first
            }
        }
        __syncthreads();   // protect s_warp / s_sc across iterations
    }
}

extern "C" void kernel_launch(void* const* d_in, const int* in_sizes, int n_in,
                              void* d_out, int out_size) {
    const float* in   = (const float*)d_in[0];   // [4,8,256,64,64]
    const float* Wlin = (const float*)d_in[1];   // [256,256]
    float* out = (float*)d_out;

    main_kernel<<<GRIDN, TPB>>>(in, Wlin, out);
}